// round 13
// baseline (speedup 1.0000x reference)
#include <cuda_runtime.h>

// NeuS volume-rendering composite, telescoped:
//   1 - alpha_i = sig_{i+1}/sig_i  =>  trans_i = sig_i / sig_0
//   weight_i = max(sig_i - sig_{i+1}, 0) / sig_0,  weight_0 = weight_{S-1} = 0.
//
// FLAT grid (one tile per block, no persistent loop): R11 showed the
// persistent loop serializes across iterations (DRAM 78%->73%, kernel
// 30.5->31.4us). One-shot warps keep all 10 LDG.128 front-batched with
// nothing downstream blocking them.
//
// 2 rays per warp (16-lane segments); sub-lane sl owns samples [4sl..4sl+3]
// and [64+4sl..64+4sl+3]. All bulk accesses are aligned float4 with
// streaming (evict-first) hints — every byte is touched exactly once.
// Background folded into the color sum: pixel = bg + sum w*(c - bg).
// __fdividef everywhere (MUFU.RCP path); __launch_bounds__(256,5) holds
// regs at 48 -> 5 blocks/SM (40 warps).

constexpr int N_RAYS    = 65536;
constexpr int N_SAMPLES = 128;

__device__ __forceinline__ float fsigmoid(float x) {
    return __fdividef(1.0f, 1.0f + __expf(-x));
}

__global__ __launch_bounds__(256, 5)
void neus_render_kernel(const float* __restrict__ sdf,
                        const float* __restrict__ color,
                        const float* __restrict__ z_vals,
                        const float* __restrict__ s_ptr,
                        const float* __restrict__ bg,
                        float* __restrict__ out)
{
    const int gtid = blockIdx.x * blockDim.x + threadIdx.x;
    const int lane = gtid & 31;
    const int sl   = lane & 15;                       // sub-lane in 16-lane segment
    const int ray  = (gtid >> 5) * 2 + (lane >> 4);   // 2 rays per warp

    const float s   = __ldg(s_ptr);
    const float bg0 = __ldg(bg + 0);
    const float bg1 = __ldg(bg + 1);
    const float bg2 = __ldg(bg + 2);

    // ---- front-batched loads: 10 aligned LDG.128 per thread, streaming ----
    const int r32 = ray * 32;
    const float4* sp = reinterpret_cast<const float4*>(sdf);
    const float4* zp = reinterpret_cast<const float4*>(z_vals);
    const float4* cp = reinterpret_cast<const float4*>(color) + ray * 96;

    const float4 sdA = __ldcs(sp + r32 + sl);         // samples 4sl..4sl+3
    const float4 sdB = __ldcs(sp + r32 + 16 + sl);    // samples 64+4sl..64+4sl+3
    const float4 zA  = __ldcs(zp + r32 + sl);
    const float4 zB  = __ldcs(zp + r32 + 16 + sl);
    const float4 cA0 = __ldcs(cp + sl * 3 + 0);       // r0 g0 b0 r1
    const float4 cA1 = __ldcs(cp + sl * 3 + 1);       // g1 b1 r2 g2
    const float4 cA2 = __ldcs(cp + sl * 3 + 2);       // b2 r3 g3 b3
    const float4 cB0 = __ldcs(cp + 48 + sl * 3 + 0);
    const float4 cB1 = __ldcs(cp + 48 + sl * 3 + 1);
    const float4 cB2 = __ldcs(cp + 48 + sl * 3 + 2);

    // ---- sigmoids ----
    const float a0 = fsigmoid(sdA.x * s), a1 = fsigmoid(sdA.y * s);
    const float a2 = fsigmoid(sdA.z * s), a3 = fsigmoid(sdA.w * s);
    const float b0 = fsigmoid(sdB.x * s), b1 = fsigmoid(sdB.y * s);
    const float b2 = fsigmoid(sdB.z * s), b3 = fsigmoid(sdB.w * s);

    // ---- segment shuffles (width=16) ----
    const unsigned FULL = 0xffffffffu;
    const float a0_next  = __shfl_down_sync(FULL, a0, 1, 16);  // sig(4sl+4)
    const float b0_next  = __shfl_down_sync(FULL, b0, 1, 16);  // sig(64+4sl+4)
    const float b0_first = __shfl_sync(FULL, b0, 0, 16);       // sig(sample 64)
    const float sig0     = __shfl_sync(FULL, a0, 0, 16);       // sig(sample 0)
    const float inv_s0   = __fdividef(1.0f, sig0);

    const float nextA = (sl == 15) ? b0_first : a0_next;

    // ---- weights (weight_0 = 0, weight_127 = 0) ----
    const float wa0 = (sl == 0) ? 0.0f : fmaxf(a0 - a1, 0.0f) * inv_s0;
    const float wa1 = fmaxf(a1 - a2,    0.0f) * inv_s0;
    const float wa2 = fmaxf(a2 - a3,    0.0f) * inv_s0;
    const float wa3 = fmaxf(a3 - nextA, 0.0f) * inv_s0;
    const float wb0 = fmaxf(b0 - b1,    0.0f) * inv_s0;
    const float wb1 = fmaxf(b1 - b2,    0.0f) * inv_s0;
    const float wb2 = fmaxf(b2 - b3,    0.0f) * inv_s0;
    const float wb3 = (sl == 15) ? 0.0f : fmaxf(b3 - b0_next, 0.0f) * inv_s0;

    // ---- store weight tiles (streaming STG.128) ----
    float4* w_out = reinterpret_cast<float4*>(out + N_RAYS * 4);
    __stcs(w_out + r32 + sl,      make_float4(wa0, wa1, wa2, wa3));
    __stcs(w_out + r32 + 16 + sl, make_float4(wb0, wb1, wb2, wb3));

    // ---- inverse depth partial ----
    float invd = __fdividef(wa0, zA.x) + __fdividef(wa1, zA.y)
               + __fdividef(wa2, zA.z) + __fdividef(wa3, zA.w)
               + __fdividef(wb0, zB.x) + __fdividef(wb1, zB.y)
               + __fdividef(wb2, zB.z) + __fdividef(wb3, zB.w);

    // ---- pixel partials with background folded in ----
    float pr = wa0 * (cA0.x - bg0) + wa1 * (cA0.w - bg0)
             + wa2 * (cA1.z - bg0) + wa3 * (cA2.y - bg0)
             + wb0 * (cB0.x - bg0) + wb1 * (cB0.w - bg0)
             + wb2 * (cB1.z - bg0) + wb3 * (cB2.y - bg0);
    float pg = wa0 * (cA0.y - bg1) + wa1 * (cA1.x - bg1)
             + wa2 * (cA1.w - bg1) + wa3 * (cA2.z - bg1)
             + wb0 * (cB0.y - bg1) + wb1 * (cB1.x - bg1)
             + wb2 * (cB1.w - bg1) + wb3 * (cB2.z - bg1);
    float pb = wa0 * (cA0.z - bg2) + wa1 * (cA1.y - bg2)
             + wa2 * (cA2.x - bg2) + wa3 * (cA2.w - bg2)
             + wb0 * (cB0.z - bg2) + wb1 * (cB1.y - bg2)
             + wb2 * (cB2.x - bg2) + wb3 * (cB2.w - bg2);

    // ---- width-16 butterfly over 4 scalars ----
    #pragma unroll
    for (int off = 8; off > 0; off >>= 1) {
        pr   += __shfl_xor_sync(FULL, pr,   off, 16);
        pg   += __shfl_xor_sync(FULL, pg,   off, 16);
        pb   += __shfl_xor_sync(FULL, pb,   off, 16);
        invd += __shfl_xor_sync(FULL, invd, off, 16);
    }

    if (sl == 0) {
        out[ray * 3 + 0]      = bg0 + pr;
        out[ray * 3 + 1]      = bg1 + pg;
        out[ray * 3 + 2]      = bg2 + pb;
        out[N_RAYS * 3 + ray] = invd;
    }
}

extern "C" void kernel_launch(void* const* d_in, const int* in_sizes, int n_in,
                              void* d_out, int out_size)
{
    const float* sdf   = (const float*)d_in[0];
    const float* color = (const float*)d_in[1];
    const float* z     = (const float*)d_in[2];
    const float* s     = (const float*)d_in[3];
    const float* bg    = (const float*)d_in[4];
    float* out = (float*)d_out;

    const int threads = 256;                 // 8 warps = 16 rays per block
    const int blocks  = N_RAYS / 16;         // 4096 blocks, one shot
    neus_render_kernel<<<blocks, threads>>>(sdf, color, z, s, bg, out);
}